// round 11
// baseline (speedup 1.0000x reference)
#include <cuda_runtime.h>

constexpr int VOCAB = 50257;
constexpr int DIM   = 50;
constexpr int NU2   = 64;
constexpr int NB    = 1024;
constexpr int NT    = 1024;

using u64 = unsigned long long;

// Precomputed embedding projection: embproj[v][k] = emb[v]@kx1[:,k] + b1[0][k]
// 50257*96 floats = 19.3 MB -> L2 resident during the recurrent kernel.
__device__ float g_embproj[(size_t)VOCAB * 96];

__device__ __forceinline__ u64 pack2(float lo, float hi) {
    u64 r; asm("mov.b64 %0, {%1, %2};" : "=l"(r) : "f"(lo), "f"(hi)); return r;
}
__device__ __forceinline__ void unpack2(u64 p, float& lo, float& hi) {
    asm("mov.b64 {%0, %1}, %2;" : "=f"(lo), "=f"(hi) : "l"(p));
}
__device__ __forceinline__ u64 fma2(u64 a, u64 b, u64 c) {
    u64 d; asm("fma.rn.f32x2 %0, %1, %2, %3;" : "=l"(d) : "l"(a), "l"(b), "l"(c)); return d;
}
__device__ __forceinline__ u64 add2(u64 a, u64 b) {
    u64 d; asm("add.rn.f32x2 %0, %1, %2;" : "=l"(d) : "l"(a), "l"(b)); return d;
}
__device__ __forceinline__ float sigf(float x) {
    return __fdividef(1.0f, 1.0f + __expf(-x));
}
__device__ __forceinline__ float tanh_fast(float x) {
    return 1.0f - __fdividef(2.0f, 1.0f + __expf(2.0f * x));
}

// ---------------------------------------------------------------------------
// Kernel A: embproj = emb @ kx1 + b1[0]
// ---------------------------------------------------------------------------
__global__ void __launch_bounds__(96) embproj_kernel(const float* __restrict__ emb,
                                                     const float* __restrict__ kx1,
                                                     const float* __restrict__ b1) {
    __shared__ float kx1s[DIM * 96];
    __shared__ float xrow[DIM];
    const int tid = threadIdx.x;
    for (int i = tid; i < DIM * 96; i += 96) kx1s[i] = kx1[i];
    const float bc = b1[tid];
    __syncthreads();
    const int row0 = blockIdx.x * 16;
    for (int k = 0; k < 16; k++) {
        const int row = row0 + k;
        if (row >= VOCAB) break;
        if (tid < DIM) xrow[tid] = emb[(size_t)row * DIM + tid];
        __syncthreads();
        float acc = bc;
        #pragma unroll
        for (int d = 0; d < DIM; d++) acc = fmaf(xrow[d], kx1s[d * 96 + tid], acc);
        g_embproj[(size_t)row * 96 + tid] = acc;
        __syncthreads();
    }
}

// ---------------------------------------------------------------------------
// Kernel B: fused GRU1 -> GRU2 -> GLU -> dense.
// 296 blocks x 128 threads (2 CTAs/SM, balanced; same-SM pair = (b, b+148)).
// CTAs with bid>=148 are phase-STAGGERED by ~1500 cyc so the two co-resident
// CTAs anti-phase: one computes while the other waits at its barrier.
// ALL weights register-resident, j-split across the 4 warps. State (h1, h2)
// is stored in smem PRE-DUPLICATED as {v,v} u64 pairs so FFMA2 operands come
// straight from LDS.128 (no dup2/mov instructions in the hot loops).
//
// smem (u64 units):
//   [0,3072)     pX    u64[4 elems][4 warps][6][32] (xz,xr,xh, rz,rr,rh)
//   [3072,3584)  pRzr  u64[4][4][32]   rec1 z,r partial (paired)
//   [3584,4096)  pRhU  u64[4][4][32]   rec1 h partial in lo lane
//   [4096,4224)  h1d   u64[4][32]      h1 duplicated {v,v}
//   [4224,4480)  h2d   u64[4][64]      h2 duplicated {v,v}
// ---------------------------------------------------------------------------
constexpr int SMEM_FLOATS = 4480 * 2;   // 35 KB

template<int NE>
__device__ __forceinline__ void rnn_scan(
    const int* __restrict__ tok, bool owns, int wid, int l,
    u64* pX, u64* pRzr, u64* pRhU, u64* h1d, u64* h2d,
    const u64* wz2, const u64* wr2, const u64* wh2,
    const u64* xw0, const u64* xw1, const u64* xw2,
    const u64* k1zr, const u64* k1hp,
    u64 azr1b, u64 bg1p, u64 bz2, u64 br2, u64 bxh2, u64 bhh2,
    float& h1o, float& h2a, float& h2b)
{
    // --- prologue: embproj gather for t=0 ---
    int tk = 0;
    float xz = 0.0f, xr = 0.0f, xh = 0.0f;
    if (owns) {
        tk = tok[l];
        const int ti = __shfl_sync(0xffffffffu, tk, 0);
        const float* ep = g_embproj + (size_t)ti * 96;
        xz = __ldg(ep + l); xr = __ldg(ep + 32 + l); xh = __ldg(ep + 64 + l);
    }

    for (int t = 0; t < NT; t++) {
        // ===== Phase A: rec2 partials (h2(t-1)) + GRU1 combine =============
        #pragma unroll
        for (int e = 0; e < NE; e++) {
            const ulonglong2* hv = (const ulonglong2*)(h2d + (size_t)e * 64 + wid * 16);
            u64 az = 0ull, ar = 0ull, ah = 0ull;
            #pragma unroll
            for (int q = 0; q < 8; q++) {
                const ulonglong2 v = hv[q];
                az = fma2(wz2[2*q],   v.x, az); ar = fma2(wr2[2*q],   v.x, ar); ah = fma2(wh2[2*q],   v.x, ah);
                az = fma2(wz2[2*q+1], v.y, az); ar = fma2(wr2[2*q+1], v.y, ar); ah = fma2(wh2[2*q+1], v.y, ah);
            }
            u64* pb = pX + (size_t)((e * 4 + wid) * 6) * 32 + l;
            pb[96]  = az;   // slot 3: rec z
            pb[128] = ar;   // slot 4: rec r
            pb[160] = ah;   // slot 5: rec h
        }

        if (owns) {
            // GRU1: combine rec1 partials (written at step t-1; zero at t=0)
            u64 zr = azr1b; u64 hmu = bg1p;
            #pragma unroll
            for (int w = 0; w < 4; w++) {
                zr  = add2(zr,  pRzr[(wid * 4 + w) * 32 + l]);
                hmu = add2(hmu, pRhU[(wid * 4 + w) * 32 + l]);
            }
            float az, ar; unpack2(zr, az, ar);
            float hm, hdump; unpack2(hmu, hm, hdump);
            const float z = sigf(xz + az), r = sigf(xr + ar);
            const float hh = tanh_fast(xh + r * hm);
            h1o = z * h1o + (1.0f - z) * hh;
            h1d[wid * 32 + l] = pack2(h1o, h1o);
        }

        // prefetch embproj for t+1 (lands long before next Phase A)
        if (owns && t + 1 < NT) {
            if (((t + 1) & 31) == 0) tk = tok[t + 1 + l];
            const int ti = __shfl_sync(0xffffffffu, tk, (t + 1) & 31);
            const float* ep = g_embproj + (size_t)ti * 96;
            xz = __ldg(ep + l); xr = __ldg(ep + 32 + l); xh = __ldg(ep + 64 + l);
        }
        __syncthreads();              // BAR1: h1(t), rec2 partials published

        // ===== Phase B: xproj2 partials + rec1 partials for t+1 ============
        #pragma unroll
        for (int e = 0; e < NE; e++) {
            const ulonglong2* hp = (const ulonglong2*)(h1d + (size_t)e * 32 + wid * 8);
            const ulonglong2 a0 = hp[0], a1 = hp[1], a2 = hp[2], a3 = hp[3];
            u64 az = 0ull, ar = 0ull, ax = 0ull, zr1 = 0ull, hm1 = 0ull;
            #define RNN_STEPB(jj, d) \
                az  = fma2(xw0[jj],  d, az);  ar  = fma2(xw1[jj], d, ar); \
                ax  = fma2(xw2[jj],  d, ax);  zr1 = fma2(k1zr[jj], d, zr1); \
                hm1 = fma2(k1hp[jj], d, hm1);
            RNN_STEPB(0, a0.x) RNN_STEPB(1, a0.y)
            RNN_STEPB(2, a1.x) RNN_STEPB(3, a1.y)
            RNN_STEPB(4, a2.x) RNN_STEPB(5, a2.y)
            RNN_STEPB(6, a3.x) RNN_STEPB(7, a3.y)
            #undef RNN_STEPB
            u64* pb = pX + (size_t)((e * 4 + wid) * 6) * 32 + l;
            pb[0]  = az;    // slot 0: x z
            pb[32] = ar;    // slot 1: x r
            pb[64] = ax;    // slot 2: x h
            pRzr[(e * 4 + wid) * 32 + l] = zr1;
            pRhU[(e * 4 + wid) * 32 + l] = hm1;
        }
        __syncthreads();              // BAR2: partials published

        // ===== Phase C: combine -> GRU2 gates -> h2(t) =====================
        if (owns) {
            u64 zp = bz2, rp = br2, xp = bxh2, hm = bhh2;
            #pragma unroll
            for (int w = 0; w < 4; w++) {
                const u64* pb = pX + (size_t)((wid * 4 + w) * 6) * 32 + l;
                zp = add2(zp, pb[0]);
                rp = add2(rp, pb[32]);
                xp = add2(xp, pb[64]);
                zp = add2(zp, pb[96]);
                rp = add2(rp, pb[128]);
                hm = add2(hm, pb[160]);
            }
            float zl, zh_, rl, rh_, xpl, xph, ml, mh;
            unpack2(zp, zl, zh_); unpack2(rp, rl, rh_);
            unpack2(xp, xpl, xph); unpack2(hm, ml, mh);
            {
                const float z = sigf(zl), r = sigf(rl);
                const float hh = tanh_fast(xpl + r * ml);
                h2a = z * h2a + (1.0f - z) * hh;
            }
            {
                const float z = sigf(zh_), r = sigf(rh_);
                const float hh = tanh_fast(xph + r * mh);
                h2b = z * h2b + (1.0f - z) * hh;
            }
            h2d[wid * 64 + l]      = pack2(h2a, h2a);
            h2d[wid * 64 + 32 + l] = pack2(h2b, h2b);
        }
        __syncthreads();              // BAR3: h2(t) published
    }
}

__global__ void __launch_bounds__(128, 2) rnn_kernel(
    const int*   __restrict__ tokens,
    const float* __restrict__ kh1, const float* __restrict__ b1,
    const float* __restrict__ kx2, const float* __restrict__ kh2,
    const float* __restrict__ b2,
    const float* __restrict__ wg,  const float* __restrict__ bg,
    const float* __restrict__ wd,  const float* __restrict__ bd,
    float* __restrict__ out)
{
    extern __shared__ float smemf[];
    u64*   pX   = (u64*)smemf;                // [4][4][6][32]
    u64*   pRzr = pX + 3072;                  // [4][4][32]
    u64*   pRhU = pRzr + 512;                 // [4][4][32]
    u64*   h1d  = pRhU + 512;                 // [4][32]
    u64*   h2d  = h1d + 128;                  // [4][64]

    const int tid = threadIdx.x;

    // zero-init state + rec1 partial buffers (h(-1) = 0 -> partials = 0)
    for (int i = tid; i < 512 + 512 + 128 + 256; i += 128) pRzr[i] = 0ull;
    __syncthreads();

    const int wid = tid >> 5;
    const int l   = tid & 31;

    // block -> elem range: blocks [0,136) own 4 elems, [136,296) own 3 elems
    const int bid = blockIdx.x;
    const bool big = (bid < 136);
    const int ne   = big ? 4 : 3;
    const int base = big ? bid * 4 : 544 + (bid - 136) * 3;
    const bool owns = (wid < ne);
    const int eg = base + (owns ? wid : ne - 1);   // clamped for safety

    // kh2 rows [16w, 16w+16): lane l owns col pairs (l, l+32) per gate
    u64 wz2[16], wr2[16], wh2[16];
    {
        const float* wbase = kh2 + (size_t)(wid * 16) * 192;
        #pragma unroll
        for (int jj = 0; jj < 16; jj++) {
            const float* r = wbase + jj * 192;
            wz2[jj] = pack2(__ldg(r + l),       __ldg(r + 32 + l));
            wr2[jj] = pack2(__ldg(r + 64 + l),  __ldg(r + 96 + l));
            wh2[jj] = pack2(__ldg(r + 128 + l), __ldg(r + 160 + l));
        }
    }
    // kx2 rows [8w, 8w+8)
    u64 xw0[8], xw1[8], xw2[8];
    {
        const float* wbase = kx2 + (size_t)(wid * 8) * 192;
        #pragma unroll
        for (int jj = 0; jj < 8; jj++) {
            const float* r = wbase + jj * 192;
            xw0[jj] = pack2(__ldg(r + l),       __ldg(r + 32 + l));
            xw1[jj] = pack2(__ldg(r + 64 + l),  __ldg(r + 96 + l));
            xw2[jj] = pack2(__ldg(r + 128 + l), __ldg(r + 160 + l));
        }
    }
    // kh1 rows [8w, 8w+8): z,r paired + h in lo lane of a pair {w, 0}
    u64 k1zr[8], k1hp[8];
    {
        const float* wbase = kh1 + (size_t)(wid * 8) * 96;
        #pragma unroll
        for (int jj = 0; jj < 8; jj++) {
            const float* r = wbase + jj * 96;
            k1zr[jj] = pack2(__ldg(r + l), __ldg(r + 32 + l));
            k1hp[jj] = pack2(__ldg(r + 64 + l), 0.0f);
        }
    }

    // biases
    const u64 azr1b = pack2(__ldg(b1 + 96 + l), __ldg(b1 + 128 + l));
    const u64 bg1p  = pack2(__ldg(b1 + 160 + l), 0.0f);
    const u64 bz2  = pack2(__ldg(b2 + l)      + __ldg(b2 + 192 + l),
                           __ldg(b2 + 32 + l) + __ldg(b2 + 224 + l));
    const u64 br2  = pack2(__ldg(b2 + 64 + l) + __ldg(b2 + 256 + l),
                           __ldg(b2 + 96 + l) + __ldg(b2 + 288 + l));
    const u64 bxh2 = pack2(__ldg(b2 + 128 + l), __ldg(b2 + 160 + l));
    const u64 bhh2 = pack2(__ldg(b2 + 320 + l), __ldg(b2 + 352 + l));

    // --- PHASE STAGGER: second-resident CTA (bid>=148 shares an SM with
    // bid-148) delays ~1500 cyc via a serial FFMA chain so the two CTAs run
    // anti-phase: one computes while the other waits at its barrier. ---
    if (bid >= 148) {
        float xx = (float)(tid + 1);
        #pragma unroll 1
        for (int i = 0; i < 300; i++) {
            xx = fmaf(xx, 0.999999f, 1.0e-6f);
            asm volatile("" : "+f"(xx));
        }
    }

    const int* tok = tokens + (size_t)eg * NT;
    float h1o = 0.0f, h2a = 0.0f, h2b = 0.0f;

    if (big) rnn_scan<4>(tok, owns, wid, l, pX, pRzr, pRhU, h1d, h2d,
                         wz2, wr2, wh2, xw0, xw1, xw2, k1zr, k1hp,
                         azr1b, bg1p, bz2, br2, bxh2, bhh2, h1o, h2a, h2b);
    else     rnn_scan<3>(tok, owns, wid, l, pX, pRzr, pRhU, h1d, h2d,
                         wz2, wr2, wh2, xw0, xw1, xw2, k1zr, k1hp,
                         azr1b, bg1p, bz2, br2, bxh2, bhh2, h1o, h2a, h2b);

    // ---------------- head: a = h2@wg + bg ; GLU ; sigmoid(x@wd + bd) -------
    if (owns) {
        const float* h2f = (const float*)(h2d + (size_t)wid * 64);  // lo of {v,v}
        float acc[8];
        #pragma unroll
        for (int k = 0; k < 8; k++) acc[k] = __ldg(bg + l + 32 * k);
        for (int j = 0; j < NU2; j++) {
            const float hv = h2f[2 * j];
            const float* wrp = wg + j * 256 + l;
            #pragma unroll
            for (int k = 0; k < 8; k++) acc[k] = fmaf(hv, __ldg(wrp + 32 * k), acc[k]);
        }
        float s = 0.0f;
        #pragma unroll
        for (int k = 0; k < 4; k++) {
            const float g = acc[k] * sigf(acc[k + 4]);
            s = fmaf(g, __ldg(wd + l + 32 * k), s);
        }
        #pragma unroll
        for (int off = 16; off >= 1; off >>= 1) s += __shfl_xor_sync(0xffffffffu, s, off);
        if (l == 0) out[eg] = sigf(s + __ldg(bd));
    }
}

// ---------------------------------------------------------------------------
extern "C" void kernel_launch(void* const* d_in, const int* in_sizes, int n_in,
                              void* d_out, int out_size) {
    const int*   tokens = (const int*)d_in[0];
    const float* emb = (const float*)d_in[1];
    const float* kx1 = (const float*)d_in[2];
    const float* kh1 = (const float*)d_in[3];
    const float* b1  = (const float*)d_in[4];
    const float* kx2 = (const float*)d_in[5];
    const float* kh2 = (const float*)d_in[6];
    const float* b2  = (const float*)d_in[7];
    const float* wg  = (const float*)d_in[8];
    const float* bg  = (const float*)d_in[9];
    const float* wd  = (const float*)d_in[10];
    const float* bd  = (const float*)d_in[11];
    float* out = (float*)d_out;

    const size_t smem_bytes = SMEM_FLOATS * sizeof(float);
    cudaFuncSetAttribute(rnn_kernel, cudaFuncAttributeMaxDynamicSharedMemorySize, (int)smem_bytes);

    embproj_kernel<<<(VOCAB + 15) / 16, 96>>>(emb, kx1, b1);
    rnn_kernel<<<296, 128, smem_bytes>>>(tokens, kh1, b1, kx2, kh2, b2, wg, bg, wd, bd, out);
}

// round 12
// speedup vs baseline: 1.1168x; 1.1168x over previous
#include <cuda_runtime.h>

constexpr int VOCAB = 50257;
constexpr int DIM   = 50;
constexpr int NU2   = 64;
constexpr int NB    = 1024;
constexpr int NT    = 1024;

using u64 = unsigned long long;

// Precomputed embedding projection: embproj[v][k] = emb[v]@kx1[:,k] + b1[0][k]
// 50257*96 floats = 19.3 MB -> L2 resident during the recurrent kernel.
__device__ float g_embproj[(size_t)VOCAB * 96];

__device__ __forceinline__ u64 pack2(float lo, float hi) {
    u64 r; asm("mov.b64 %0, {%1, %2};" : "=l"(r) : "f"(lo), "f"(hi)); return r;
}
__device__ __forceinline__ u64 dup2(float v) { return pack2(v, v); }
__device__ __forceinline__ void unpack2(u64 p, float& lo, float& hi) {
    asm("mov.b64 {%0, %1}, %2;" : "=f"(lo), "=f"(hi) : "l"(p));
}
__device__ __forceinline__ u64 fma2(u64 a, u64 b, u64 c) {
    u64 d; asm("fma.rn.f32x2 %0, %1, %2, %3;" : "=l"(d) : "l"(a), "l"(b), "l"(c)); return d;
}
__device__ __forceinline__ u64 add2(u64 a, u64 b) {
    u64 d; asm("add.rn.f32x2 %0, %1, %2;" : "=l"(d) : "l"(a), "l"(b)); return d;
}
__device__ __forceinline__ float sigf(float x) {
    return __fdividef(1.0f, 1.0f + __expf(-x));
}
__device__ __forceinline__ float tanh_fast(float x) {
    return 1.0f - __fdividef(2.0f, 1.0f + __expf(2.0f * x));
}

// ---------------------------------------------------------------------------
// Kernel A: embproj = emb @ kx1 + b1[0]
// ---------------------------------------------------------------------------
__global__ void __launch_bounds__(96) embproj_kernel(const float* __restrict__ emb,
                                                     const float* __restrict__ kx1,
                                                     const float* __restrict__ b1) {
    __shared__ float kx1s[DIM * 96];
    __shared__ float xrow[DIM];
    const int tid = threadIdx.x;
    for (int i = tid; i < DIM * 96; i += 96) kx1s[i] = kx1[i];
    const float bc = b1[tid];
    __syncthreads();
    const int row0 = blockIdx.x * 16;
    for (int k = 0; k < 16; k++) {
        const int row = row0 + k;
        if (row >= VOCAB) break;
        if (tid < DIM) xrow[tid] = emb[(size_t)row * DIM + tid];
        __syncthreads();
        float acc = bc;
        #pragma unroll
        for (int d = 0; d < DIM; d++) acc = fmaf(xrow[d], kx1s[d * 96 + tid], acc);
        g_embproj[(size_t)row * 96 + tid] = acc;
        __syncthreads();
    }
}

// ---------------------------------------------------------------------------
// Kernel B: fused GRU1 -> GRU2 -> GLU -> dense.  (R10 structure, unchanged,
// plus a prologue phase-stagger for the second co-resident CTA.)
// 296 blocks x 128 threads (2 CTAs/SM, balanced). Blocks [0,136): 4 elems,
// [136,296): 3 elems; warp w owns elem w (if w < NE).
// ALL weights register-resident, j-split across the 4 warps:
//   kh2 rows [16w,16w+16), kx2 rows [8w,8w+8), kh1 rows [8w,8w+8).
// Cross-step software pipeline (3 barriers per step):
//   Phase A: rec2 partials (h2(t-1)) -> pX slots 3..5;
//            GRU1 combine of rec1 partials (stored last step) -> h1(t); BAR1
//   Phase B: xproj2 partials from h1(t) -> pX slots 0..2;
//            rec1 partials FOR t+1 from the same h1 values -> pR;     BAR2
//   Phase C: combine pX -> GRU2 gates -> h2(t); publish;              BAR3
// ---------------------------------------------------------------------------
constexpr int SMEM_FLOATS = 8064;   // 31.5 KB

template<int NE>
__device__ __forceinline__ void rnn_scan(
    const int* __restrict__ tok, bool owns, int wid, int l,
    u64* pX, u64* pRzr, float* pRh, float* h1s, float* h2s,
    const u64* wz2, const u64* wr2, const u64* wh2,
    const u64* xw0, const u64* xw1, const u64* xw2,
    const u64* k1zr, const float* k1h,
    u64 azr1b, float bg1, u64 bz2, u64 br2, u64 bxh2, u64 bhh2,
    float& h1o, float& h2a, float& h2b)
{
    // --- prologue: embproj gather for t=0 ---
    int tk = 0;
    float xz = 0.0f, xr = 0.0f, xh = 0.0f;
    if (owns) {
        tk = tok[l];
        const int ti = __shfl_sync(0xffffffffu, tk, 0);
        const float* ep = g_embproj + (size_t)ti * 96;
        xz = __ldg(ep + l); xr = __ldg(ep + 32 + l); xh = __ldg(ep + 64 + l);
    }

    for (int t = 0; t < NT; t++) {
        // ===== Phase A: rec2 partials (h2(t-1)) + GRU1 combine =============
        #pragma unroll
        for (int e = 0; e < NE; e++) {
            const float4* hv = (const float4*)(h2s + e * 64 + wid * 16);
            u64 az = 0ull, ar = 0ull, ah = 0ull;
            #pragma unroll
            for (int q = 0; q < 4; q++) {
                const float4 v = hv[q];
                u64 d;
                d = dup2(v.x); az = fma2(wz2[q*4+0], d, az); ar = fma2(wr2[q*4+0], d, ar); ah = fma2(wh2[q*4+0], d, ah);
                d = dup2(v.y); az = fma2(wz2[q*4+1], d, az); ar = fma2(wr2[q*4+1], d, ar); ah = fma2(wh2[q*4+1], d, ah);
                d = dup2(v.z); az = fma2(wz2[q*4+2], d, az); ar = fma2(wr2[q*4+2], d, ar); ah = fma2(wh2[q*4+2], d, ah);
                d = dup2(v.w); az = fma2(wz2[q*4+3], d, az); ar = fma2(wr2[q*4+3], d, ar); ah = fma2(wh2[q*4+3], d, ah);
            }
            u64* pb = pX + (size_t)((e * 4 + wid) * 6) * 32 + l;
            pb[96]  = az;   // slot 3: rec z
            pb[128] = ar;   // slot 4: rec r
            pb[160] = ah;   // slot 5: rec h
        }

        if (owns) {
            // GRU1: combine rec1 partials (written at step t-1; zero at t=0)
            u64 zr = azr1b; float hm = bg1;
            #pragma unroll
            for (int w = 0; w < 4; w++) {
                zr = add2(zr, pRzr[(wid * 4 + w) * 32 + l]);
                hm += pRh[(wid * 4 + w) * 32 + l];
            }
            float az, ar; unpack2(zr, az, ar);
            const float z = sigf(xz + az), r = sigf(xr + ar);
            const float hh = tanh_fast(xh + r * hm);
            h1o = z * h1o + (1.0f - z) * hh;
            h1s[wid * 32 + l] = h1o;
        }

        // prefetch embproj for t+1 (lands long before next Phase A)
        if (owns && t + 1 < NT) {
            if (((t + 1) & 31) == 0) tk = tok[t + 1 + l];
            const int ti = __shfl_sync(0xffffffffu, tk, (t + 1) & 31);
            const float* ep = g_embproj + (size_t)ti * 96;
            xz = __ldg(ep + l); xr = __ldg(ep + 32 + l); xh = __ldg(ep + 64 + l);
        }
        __syncthreads();              // BAR1: h1(t), rec2 partials published

        // ===== Phase B: xproj2 partials + rec1 partials for t+1 ============
        #pragma unroll
        for (int e = 0; e < NE; e++) {
            const float4* hp = (const float4*)(h1s + e * 32 + wid * 8);
            float vv[8];
            *(float4*)(vv)     = hp[0];
            *(float4*)(vv + 4) = hp[1];
            u64 az = 0ull, ar = 0ull, ax = 0ull;
            u64 zr1 = 0ull; float hm1 = 0.0f;
            #pragma unroll
            for (int jj = 0; jj < 8; jj++) {
                const u64 d = dup2(vv[jj]);
                az  = fma2(xw0[jj], d, az);
                ar  = fma2(xw1[jj], d, ar);
                ax  = fma2(xw2[jj], d, ax);
                zr1 = fma2(k1zr[jj], d, zr1);
                hm1 = fmaf(k1h[jj], vv[jj], hm1);
            }
            u64* pb = pX + (size_t)((e * 4 + wid) * 6) * 32 + l;
            pb[0]  = az;    // slot 0: x z
            pb[32] = ar;    // slot 1: x r
            pb[64] = ax;    // slot 2: x h
            pRzr[(e * 4 + wid) * 32 + l] = zr1;
            pRh [(e * 4 + wid) * 32 + l] = hm1;
        }
        __syncthreads();              // BAR2: partials published

        // ===== Phase C: combine -> GRU2 gates -> h2(t) =====================
        if (owns) {
            u64 zp = bz2, rp = br2, xp = bxh2, hm = bhh2;
            #pragma unroll
            for (int w = 0; w < 4; w++) {
                const u64* pb = pX + (size_t)((wid * 4 + w) * 6) * 32 + l;
                zp = add2(zp, pb[0]);
                rp = add2(rp, pb[32]);
                xp = add2(xp, pb[64]);
                zp = add2(zp, pb[96]);
                rp = add2(rp, pb[128]);
                hm = add2(hm, pb[160]);
            }
            float zl, zh_, rl, rh_, xpl, xph, ml, mh;
            unpack2(zp, zl, zh_); unpack2(rp, rl, rh_);
            unpack2(xp, xpl, xph); unpack2(hm, ml, mh);
            {
                const float z = sigf(zl), r = sigf(rl);
                const float hh = tanh_fast(xpl + r * ml);
                h2a = z * h2a + (1.0f - z) * hh;
            }
            {
                const float z = sigf(zh_), r = sigf(rh_);
                const float hh = tanh_fast(xph + r * mh);
                h2b = z * h2b + (1.0f - z) * hh;
            }
            h2s[wid * 64 + l]      = h2a;
            h2s[wid * 64 + 32 + l] = h2b;
        }
        __syncthreads();              // BAR3: h2(t) published
    }
}

__global__ void __launch_bounds__(128, 2) rnn_kernel(
    const int*   __restrict__ tokens,
    const float* __restrict__ kh1, const float* __restrict__ b1,
    const float* __restrict__ kx2, const float* __restrict__ kh2,
    const float* __restrict__ b2,
    const float* __restrict__ wg,  const float* __restrict__ bg,
    const float* __restrict__ wd,  const float* __restrict__ bd,
    float* __restrict__ out)
{
    extern __shared__ float smem[];
    u64*   pX   = (u64*)smem;                 // [4][4][6][32] u64
    u64*   pRzr = pX + 3072;                  // [4][4][32] u64
    float* pRh  = (float*)(pRzr + 512);       // [4][4][32] f32
    float* h1s  = pRh + 512;                  // [4][32]
    float* h2s  = h1s + 128;                  // [4][64]

    const int tid = threadIdx.x;

    // zero-init state + rec1 partial buffers (h(-1) = 0 -> partials = 0)
    for (int i = tid; i < 1024; i += 128) ((float*)pRzr)[i] = 0.0f;   // pRzr
    for (int i = tid; i < 512;  i += 128) pRh[i] = 0.0f;
    if (tid < 128) h1s[tid] = 0.0f;
    for (int i = tid; i < 256; i += 128) h2s[i] = 0.0f;
    __syncthreads();

    const int wid = tid >> 5;
    const int l   = tid & 31;

    // block -> elem range: blocks [0,136) own 4 elems, [136,296) own 3 elems
    const int bid = blockIdx.x;
    const bool big = (bid < 136);
    const int ne   = big ? 4 : 3;
    const int base = big ? bid * 4 : 544 + (bid - 136) * 3;
    const bool owns = (wid < ne);
    const int eg = base + (owns ? wid : ne - 1);   // clamped for safety

    // kh2 rows [16w, 16w+16): lane l owns col pairs (l, l+32) per gate
    u64 wz2[16], wr2[16], wh2[16];
    {
        const float* wbase = kh2 + (size_t)(wid * 16) * 192;
        #pragma unroll
        for (int jj = 0; jj < 16; jj++) {
            const float* r = wbase + jj * 192;
            wz2[jj] = pack2(__ldg(r + l),       __ldg(r + 32 + l));
            wr2[jj] = pack2(__ldg(r + 64 + l),  __ldg(r + 96 + l));
            wh2[jj] = pack2(__ldg(r + 128 + l), __ldg(r + 160 + l));
        }
    }
    // kx2 rows [8w, 8w+8)
    u64 xw0[8], xw1[8], xw2[8];
    {
        const float* wbase = kx2 + (size_t)(wid * 8) * 192;
        #pragma unroll
        for (int jj = 0; jj < 8; jj++) {
            const float* r = wbase + jj * 192;
            xw0[jj] = pack2(__ldg(r + l),       __ldg(r + 32 + l));
            xw1[jj] = pack2(__ldg(r + 64 + l),  __ldg(r + 96 + l));
            xw2[jj] = pack2(__ldg(r + 128 + l), __ldg(r + 160 + l));
        }
    }
    // kh1 rows [8w, 8w+8): z,r paired + h scalar
    u64 k1zr[8]; float k1h[8];
    {
        const float* wbase = kh1 + (size_t)(wid * 8) * 96;
        #pragma unroll
        for (int jj = 0; jj < 8; jj++) {
            const float* r = wbase + jj * 96;
            k1zr[jj] = pack2(__ldg(r + l), __ldg(r + 32 + l));
            k1h[jj]  = __ldg(r + 64 + l);
        }
    }

    // biases
    const u64 azr1b = pack2(__ldg(b1 + 96 + l), __ldg(b1 + 128 + l));
    const float bg1 = __ldg(b1 + 160 + l);
    const u64 bz2  = pack2(__ldg(b2 + l)      + __ldg(b2 + 192 + l),
                           __ldg(b2 + 32 + l) + __ldg(b2 + 224 + l));
    const u64 br2  = pack2(__ldg(b2 + 64 + l) + __ldg(b2 + 256 + l),
                           __ldg(b2 + 96 + l) + __ldg(b2 + 288 + l));
    const u64 bxh2 = pack2(__ldg(b2 + 128 + l), __ldg(b2 + 160 + l));
    const u64 bhh2 = pack2(__ldg(b2 + 320 + l), __ldg(b2 + 352 + l));

    // --- PHASE STAGGER (the ONLY change vs R10): the second co-resident CTA
    // (bid>=148 shares an SM with bid-148 under the classic bid%148 LUT)
    // delays ~1400 cyc (half a step) via a serial FFMA chain so the pair runs
    // anti-phase: one CTA computes while the other waits at its barrier. ---
    if (bid >= 148) {
        float xx = (float)(tid + 1);
        #pragma unroll 1
        for (int i = 0; i < 350; i++) {
            xx = fmaf(xx, 0.999999f, 1.0e-6f);
            asm volatile("" : "+f"(xx));
        }
    }

    const int* tok = tokens + (size_t)eg * NT;
    float h1o = 0.0f, h2a = 0.0f, h2b = 0.0f;

    if (big) rnn_scan<4>(tok, owns, wid, l, pX, pRzr, pRh, h1s, h2s,
                         wz2, wr2, wh2, xw0, xw1, xw2, k1zr, k1h,
                         azr1b, bg1, bz2, br2, bxh2, bhh2, h1o, h2a, h2b);
    else     rnn_scan<3>(tok, owns, wid, l, pX, pRzr, pRh, h1s, h2s,
                         wz2, wr2, wh2, xw0, xw1, xw2, k1zr, k1h,
                         azr1b, bg1, bz2, br2, bxh2, bhh2, h1o, h2a, h2b);

    // ---------------- head: a = h2@wg + bg ; GLU ; sigmoid(x@wd + bd) -------
    if (owns) {
        const float* h2e = h2s + wid * 64;
        float acc[8];
        #pragma unroll
        for (int k = 0; k < 8; k++) acc[k] = __ldg(bg + l + 32 * k);
        for (int j = 0; j < NU2; j++) {
            const float hv = h2e[j];
            const float* wrp = wg + j * 256 + l;
            #pragma unroll
            for (int k = 0; k < 8; k++) acc[k] = fmaf(hv, __ldg(wrp + 32 * k), acc[k]);
        }
        float s = 0.0f;
        #pragma unroll
        for (int k = 0; k < 4; k++) {
            const float g = acc[k] * sigf(acc[k + 4]);
            s = fmaf(g, __ldg(wd + l + 32 * k), s);
        }
        #pragma unroll
        for (int off = 16; off >= 1; off >>= 1) s += __shfl_xor_sync(0xffffffffu, s, off);
        if (l == 0) out[eg] = sigf(s + __ldg(bd));
    }
}

// ---------------------------------------------------------------------------
extern "C" void kernel_launch(void* const* d_in, const int* in_sizes, int n_in,
                              void* d_out, int out_size) {
    const int*   tokens = (const int*)d_in[0];
    const float* emb = (const float*)d_in[1];
    const float* kx1 = (const float*)d_in[2];
    const float* kh1 = (const float*)d_in[3];
    const float* b1  = (const float*)d_in[4];
    const float* kx2 = (const float*)d_in[5];
    const float* kh2 = (const float*)d_in[6];
    const float* b2  = (const float*)d_in[7];
    const float* wg  = (const float*)d_in[8];
    const float* bg  = (const float*)d_in[9];
    const float* wd  = (const float*)d_in[10];
    const float* bd  = (const float*)d_in[11];
    float* out = (float*)d_out;

    const size_t smem_bytes = SMEM_FLOATS * sizeof(float);
    cudaFuncSetAttribute(rnn_kernel, cudaFuncAttributeMaxDynamicSharedMemorySize, (int)smem_bytes);

    embproj_kernel<<<(VOCAB + 15) / 16, 96>>>(emb, kx1, b1);
    rnn_kernel<<<296, 128, smem_bytes>>>(tokens, kh1, b1, kx2, kh2, b2, wg, bg, wd, bd, out);
}

// round 13
// speedup vs baseline: 1.1927x; 1.0680x over previous
#include <cuda_runtime.h>

constexpr int VOCAB = 50257;
constexpr int DIM   = 50;
constexpr int NU2   = 64;
constexpr int NB    = 1024;
constexpr int NT    = 1024;

using u64 = unsigned long long;

// Precomputed embedding projection: embproj[v][k] = emb[v]@kx1[:,k] + b1[0][k]
// 50257*96 floats = 19.3 MB -> L2 resident during the recurrent kernel.
__device__ float g_embproj[(size_t)VOCAB * 96];

__device__ __forceinline__ u64 pack2(float lo, float hi) {
    u64 r; asm("mov.b64 %0, {%1, %2};" : "=l"(r) : "f"(lo), "f"(hi)); return r;
}
__device__ __forceinline__ void unpack2(u64 p, float& lo, float& hi) {
    asm("mov.b64 {%0, %1}, %2;" : "=f"(lo), "=f"(hi) : "l"(p));
}
__device__ __forceinline__ u64 fma2(u64 a, u64 b, u64 c) {
    u64 d; asm("fma.rn.f32x2 %0, %1, %2, %3;" : "=l"(d) : "l"(a), "l"(b), "l"(c)); return d;
}
__device__ __forceinline__ u64 add2(u64 a, u64 b) {
    u64 d; asm("add.rn.f32x2 %0, %1, %2;" : "=l"(d) : "l"(a), "l"(b)); return d;
}
__device__ __forceinline__ float hsum2(u64 p) {
    float lo, hi; unpack2(p, lo, hi); return lo + hi;
}
// Fast activations via single-MUFU tanh (sm_75+). abs err ~1e-5, fine vs 1e-3.
__device__ __forceinline__ float tanh_mufu(float x) {
    float t; asm("tanh.approx.f32 %0, %1;" : "=f"(t) : "f"(x)); return t;
}
__device__ __forceinline__ float sigf(float x) {
    return fmaf(tanh_mufu(0.5f * x), 0.5f, 0.5f);
}

// ---------------------------------------------------------------------------
// Kernel A: embproj = emb @ kx1 + b1[0]
// ---------------------------------------------------------------------------
__global__ void __launch_bounds__(96) embproj_kernel(const float* __restrict__ emb,
                                                     const float* __restrict__ kx1,
                                                     const float* __restrict__ b1) {
    __shared__ float kx1s[DIM * 96];
    __shared__ float xrow[DIM];
    const int tid = threadIdx.x;
    for (int i = tid; i < DIM * 96; i += 96) kx1s[i] = kx1[i];
    const float bc = b1[tid];
    __syncthreads();
    const int row0 = blockIdx.x * 16;
    for (int k = 0; k < 16; k++) {
        const int row = row0 + k;
        if (row >= VOCAB) break;
        if (tid < DIM) xrow[tid] = emb[(size_t)row * DIM + tid];
        __syncthreads();
        float acc = bc;
        #pragma unroll
        for (int d = 0; d < DIM; d++) acc = fmaf(xrow[d], kx1s[d * 96 + tid], acc);
        g_embproj[(size_t)row * 96 + tid] = acc;
        __syncthreads();
    }
}

// ---------------------------------------------------------------------------
// Kernel B: fused GRU1 -> GRU2 -> GLU -> dense.  (R10 phase structure.)
// 296 blocks x 128 threads (2 CTAs/SM, balanced). Blocks [0,136): 4 elems,
// [136,296): 3 elems; warp w owns elem w (if w < NE).
// ALL weights register-resident, j-split across the 4 warps.
// NEW vs R10: weights packed as even/odd-j pairs {w_j, w_j+1} per column, so
// FFMA2 consumes the state pair {h_j, h_j+1} straight from LDS.128 register
// pairs -- zero dup2/MOV broadcasts. Accumulator halves hold even/odd-j
// partial sums; one FADD folds them before the partial store.
// Activations via single-MUFU tanh.approx.
// Phases (3 barriers per step):
//   Phase A: GRU1 combine (rec1 partials from t-1) -> h1(t); rec2 partials
//            from h2(t-1) -> pX slots 3..5;                           BAR1
//   Phase B: xproj2 + rec1(t+1) partials from h1(t) -> pX 0..2, pR;   BAR2
//   Phase C: combine pX -> GRU2 gates -> h2(t); publish;              BAR3
// ---------------------------------------------------------------------------
constexpr int SMEM_FLOATS = 8064;   // 31.5 KB

template<int NE>
__device__ __forceinline__ void rnn_scan(
    const int* __restrict__ tok, bool owns, int wid, int l,
    u64* pX, u64* pRzr, float* pRh, float* h1s, float* h2s,
    const u64* wzA, const u64* wzB, const u64* wrA, const u64* wrB,
    const u64* whA, const u64* whB,
    const u64* xzA, const u64* xzB, const u64* xrA, const u64* xrB,
    const u64* xhA, const u64* xhB,
    const u64* k1z, const u64* k1r, const u64* k1h,
    u64 azr1b, float bg1, u64 bz2, u64 br2, u64 bxh2, u64 bhh2,
    float& h1o, float& h2a, float& h2b)
{
    // --- prologue: embproj gather for t=0 ---
    int tk = 0;
    float xz = 0.0f, xr = 0.0f, xh = 0.0f;
    if (owns) {
        tk = tok[l];
        const int ti = __shfl_sync(0xffffffffu, tk, 0);
        const float* ep = g_embproj + (size_t)ti * 96;
        xz = __ldg(ep + l); xr = __ldg(ep + 32 + l); xh = __ldg(ep + 64 + l);
    }

    for (int t = 0; t < NT; t++) {
        // ===== Phase A =====================================================
        // GRU1 first: its LDS + MUFU chain hides under the rec2 fma2 stream.
        if (owns) {
            u64 zr = azr1b; float hm = bg1;
            #pragma unroll
            for (int w = 0; w < 4; w++) {
                zr = add2(zr, pRzr[(wid * 4 + w) * 32 + l]);
                hm += pRh[(wid * 4 + w) * 32 + l];
            }
            float az, ar; unpack2(zr, az, ar);
            const float z = sigf(xz + az), r = sigf(xr + ar);
            const float hh = tanh_mufu(xh + r * hm);
            h1o = z * h1o + (1.0f - z) * hh;
            h1s[wid * 32 + l] = h1o;
        }

        // rec2 partials from h2(t-1), kh2 rows [16w,16w+16), even/odd packed
        #pragma unroll
        for (int e = 0; e < NE; e++) {
            const ulonglong2* hp = (const ulonglong2*)(h2s + e * 64 + wid * 16);
            u64 azAacc = 0ull, azBacc = 0ull, arAacc = 0ull, arBacc = 0ull,
                ahAacc = 0ull, ahBacc = 0ull;
            #pragma unroll
            for (int q = 0; q < 4; q++) {
                const ulonglong2 v = hp[q];
                azAacc = fma2(wzA[2*q],   v.x, azAacc); azBacc = fma2(wzB[2*q],   v.x, azBacc);
                arAacc = fma2(wrA[2*q],   v.x, arAacc); arBacc = fma2(wrB[2*q],   v.x, arBacc);
                ahAacc = fma2(whA[2*q],   v.x, ahAacc); ahBacc = fma2(whB[2*q],   v.x, ahBacc);
                azAacc = fma2(wzA[2*q+1], v.y, azAacc); azBacc = fma2(wzB[2*q+1], v.y, azBacc);
                arAacc = fma2(wrA[2*q+1], v.y, arAacc); arBacc = fma2(wrB[2*q+1], v.y, arBacc);
                ahAacc = fma2(whA[2*q+1], v.y, ahAacc); ahBacc = fma2(whB[2*q+1], v.y, ahBacc);
            }
            u64* pb = pX + (size_t)((e * 4 + wid) * 6) * 32 + l;
            pb[96]  = pack2(hsum2(azAacc), hsum2(azBacc));   // rec z (cols l, l+32)
            pb[128] = pack2(hsum2(arAacc), hsum2(arBacc));   // rec r
            pb[160] = pack2(hsum2(ahAacc), hsum2(ahBacc));   // rec h
        }

        // prefetch embproj for t+1 (lands long before next Phase A)
        if (owns && t + 1 < NT) {
            if (((t + 1) & 31) == 0) tk = tok[t + 1 + l];
            const int ti = __shfl_sync(0xffffffffu, tk, (t + 1) & 31);
            const float* ep = g_embproj + (size_t)ti * 96;
            xz = __ldg(ep + l); xr = __ldg(ep + 32 + l); xh = __ldg(ep + 64 + l);
        }
        __syncthreads();              // BAR1: h1(t), rec2 partials published

        // ===== Phase B: xproj2 + rec1(t+1) partials from h1(t) =============
        #pragma unroll
        for (int e = 0; e < NE; e++) {
            const ulonglong2* hq = (const ulonglong2*)(h1s + e * 32 + wid * 8);
            const ulonglong2 q0 = hq[0], q1 = hq[1];
            u64 hpair[4] = { q0.x, q0.y, q1.x, q1.y };
            u64 sxzA = 0ull, sxzB = 0ull, sxrA = 0ull, sxrB = 0ull,
                sxhA = 0ull, sxhB = 0ull, srz = 0ull, srr = 0ull, srh = 0ull;
            #pragma unroll
            for (int p = 0; p < 4; p++) {
                const u64 v = hpair[p];
                sxzA = fma2(xzA[p], v, sxzA); sxzB = fma2(xzB[p], v, sxzB);
                sxrA = fma2(xrA[p], v, sxrA); sxrB = fma2(xrB[p], v, sxrB);
                sxhA = fma2(xhA[p], v, sxhA); sxhB = fma2(xhB[p], v, sxhB);
                srz  = fma2(k1z[p], v, srz);  srr  = fma2(k1r[p], v, srr);
                srh  = fma2(k1h[p], v, srh);
            }
            u64* pb = pX + (size_t)((e * 4 + wid) * 6) * 32 + l;
            pb[0]  = pack2(hsum2(sxzA), hsum2(sxzB));   // x z
            pb[32] = pack2(hsum2(sxrA), hsum2(sxrB));   // x r
            pb[64] = pack2(hsum2(sxhA), hsum2(sxhB));   // x h
            pRzr[(e * 4 + wid) * 32 + l] = pack2(hsum2(srz), hsum2(srr));
            pRh [(e * 4 + wid) * 32 + l] = hsum2(srh);
        }
        __syncthreads();              // BAR2: partials published

        // ===== Phase C: combine -> GRU2 gates -> h2(t) =====================
        if (owns) {
            u64 zp = bz2, rp = br2, xp = bxh2, hm = bhh2;
            #pragma unroll
            for (int w = 0; w < 4; w++) {
                const u64* pb = pX + (size_t)((wid * 4 + w) * 6) * 32 + l;
                zp = add2(zp, pb[0]);
                rp = add2(rp, pb[32]);
                xp = add2(xp, pb[64]);
                zp = add2(zp, pb[96]);
                rp = add2(rp, pb[128]);
                hm = add2(hm, pb[160]);
            }
            float zl, zh_, rl, rh_, xpl, xph, ml, mh;
            unpack2(zp, zl, zh_); unpack2(rp, rl, rh_);
            unpack2(xp, xpl, xph); unpack2(hm, ml, mh);
            {
                const float z = sigf(zl), r = sigf(rl);
                const float hh = tanh_mufu(xpl + r * ml);
                h2a = z * h2a + (1.0f - z) * hh;
            }
            {
                const float z = sigf(zh_), r = sigf(rh_);
                const float hh = tanh_mufu(xph + r * mh);
                h2b = z * h2b + (1.0f - z) * hh;
            }
            h2s[wid * 64 + l]      = h2a;
            h2s[wid * 64 + 32 + l] = h2b;
        }
        __syncthreads();              // BAR3: h2(t) published
    }
}

__global__ void __launch_bounds__(128, 2) rnn_kernel(
    const int*   __restrict__ tokens,
    const float* __restrict__ kh1, const float* __restrict__ b1,
    const float* __restrict__ kx2, const float* __restrict__ kh2,
    const float* __restrict__ b2,
    const float* __restrict__ wg,  const float* __restrict__ bg,
    const float* __restrict__ wd,  const float* __restrict__ bd,
    float* __restrict__ out)
{
    extern __shared__ float smem[];
    u64*   pX   = (u64*)smem;                 // [4][4][6][32] u64
    u64*   pRzr = pX + 3072;                  // [4][4][32] u64
    float* pRh  = (float*)(pRzr + 512);       // [4][4][32] f32
    float* h1s  = pRh + 512;                  // [4][32]
    float* h2s  = h1s + 128;                  // [4][64]

    const int tid = threadIdx.x;

    // zero-init state + rec1 partial buffers (h(-1) = 0 -> partials = 0)
    for (int i = tid; i < 1024; i += 128) ((float*)pRzr)[i] = 0.0f;   // pRzr
    for (int i = tid; i < 512;  i += 128) pRh[i] = 0.0f;
    if (tid < 128) h1s[tid] = 0.0f;
    for (int i = tid; i < 256; i += 128) h2s[i] = 0.0f;
    __syncthreads();

    const int wid = tid >> 5;
    const int l   = tid & 31;

    // block -> elem range: blocks [0,136) own 4 elems, [136,296) own 3 elems
    const int bid = blockIdx.x;
    const bool big = (bid < 136);
    const int ne   = big ? 4 : 3;
    const int base = big ? bid * 4 : 544 + (bid - 136) * 3;
    const bool owns = (wid < ne);
    const int eg = base + (owns ? wid : ne - 1);   // clamped for safety

    // kh2 rows [16w,16w+16): even/odd-j pairs per column (A=col l, B=col l+32)
    u64 wzA[8], wzB[8], wrA[8], wrB[8], whA[8], whB[8];
    {
        const float* wbase = kh2 + (size_t)(wid * 16) * 192;
        #pragma unroll
        for (int p = 0; p < 8; p++) {
            const float* r0 = wbase + (2 * p) * 192;
            const float* r1 = r0 + 192;
            wzA[p] = pack2(__ldg(r0 + l),        __ldg(r1 + l));
            wzB[p] = pack2(__ldg(r0 + 32 + l),   __ldg(r1 + 32 + l));
            wrA[p] = pack2(__ldg(r0 + 64 + l),   __ldg(r1 + 64 + l));
            wrB[p] = pack2(__ldg(r0 + 96 + l),   __ldg(r1 + 96 + l));
            whA[p] = pack2(__ldg(r0 + 128 + l),  __ldg(r1 + 128 + l));
            whB[p] = pack2(__ldg(r0 + 160 + l),  __ldg(r1 + 160 + l));
        }
    }
    // kx2 rows [8w,8w+8): even/odd-j pairs
    u64 xzA[4], xzB[4], xrA[4], xrB[4], xhA[4], xhB[4];
    {
        const float* wbase = kx2 + (size_t)(wid * 8) * 192;
        #pragma unroll
        for (int p = 0; p < 4; p++) {
            const float* r0 = wbase + (2 * p) * 192;
            const float* r1 = r0 + 192;
            xzA[p] = pack2(__ldg(r0 + l),        __ldg(r1 + l));
            xzB[p] = pack2(__ldg(r0 + 32 + l),   __ldg(r1 + 32 + l));
            xrA[p] = pack2(__ldg(r0 + 64 + l),   __ldg(r1 + 64 + l));
            xrB[p] = pack2(__ldg(r0 + 96 + l),   __ldg(r1 + 96 + l));
            xhA[p] = pack2(__ldg(r0 + 128 + l),  __ldg(r1 + 128 + l));
            xhB[p] = pack2(__ldg(r0 + 160 + l),  __ldg(r1 + 160 + l));
        }
    }
    // kh1 rows [8w,8w+8): even/odd-j pairs for cols z=l, r=32+l, h=64+l
    u64 k1z[4], k1r[4], k1h[4];
    {
        const float* wbase = kh1 + (size_t)(wid * 8) * 96;
        #pragma unroll
        for (int p = 0; p < 4; p++) {
            const float* r0 = wbase + (2 * p) * 96;
            const float* r1 = r0 + 96;
            k1z[p] = pack2(__ldg(r0 + l),       __ldg(r1 + l));
            k1r[p] = pack2(__ldg(r0 + 32 + l),  __ldg(r1 + 32 + l));
            k1h[p] = pack2(__ldg(r0 + 64 + l),  __ldg(r1 + 64 + l));
        }
    }

    // biases
    const u64 azr1b = pack2(__ldg(b1 + 96 + l), __ldg(b1 + 128 + l));
    const float bg1 = __ldg(b1 + 160 + l);
    const u64 bz2  = pack2(__ldg(b2 + l)      + __ldg(b2 + 192 + l),
                           __ldg(b2 + 32 + l) + __ldg(b2 + 224 + l));
    const u64 br2  = pack2(__ldg(b2 + 64 + l) + __ldg(b2 + 256 + l),
                           __ldg(b2 + 96 + l) + __ldg(b2 + 288 + l));
    const u64 bxh2 = pack2(__ldg(b2 + 128 + l), __ldg(b2 + 160 + l));
    const u64 bhh2 = pack2(__ldg(b2 + 320 + l), __ldg(b2 + 352 + l));

    const int* tok = tokens + (size_t)eg * NT;
    float h1o = 0.0f, h2a = 0.0f, h2b = 0.0f;

    if (big) rnn_scan<4>(tok, owns, wid, l, pX, pRzr, pRh, h1s, h2s,
                         wzA, wzB, wrA, wrB, whA, whB,
                         xzA, xzB, xrA, xrB, xhA, xhB,
                         k1z, k1r, k1h,
                         azr1b, bg1, bz2, br2, bxh2, bhh2, h1o, h2a, h2b);
    else     rnn_scan<3>(tok, owns, wid, l, pX, pRzr, pRh, h1s, h2s,
                         wzA, wzB, wrA, wrB, whA, whB,
                         xzA, xzB, xrA, xrB, xhA, xhB,
                         k1z, k1r, k1h,
                         azr1b, bg1, bz2, br2, bxh2, bhh2, h1o, h2a, h2b);

    // ---------------- head: a = h2@wg + bg ; GLU ; sigmoid(x@wd + bd) -------
    if (owns) {
        const float* h2e = h2s + wid * 64;
        float acc[8];
        #pragma unroll
        for (int k = 0; k < 8; k++) acc[k] = __ldg(bg + l + 32 * k);
        for (int j = 0; j < NU2; j++) {
            const float hv = h2e[j];
            const float* wrp = wg + j * 256 + l;
            #pragma unroll
            for (int k = 0; k < 8; k++) acc[k] = fmaf(hv, __ldg(wrp + 32 * k), acc[k]);
        }
        float s = 0.0f;
        #pragma unroll
        for (int k = 0; k < 4; k++) {
            const float g = acc[k] * sigf(acc[k + 4]);
            s = fmaf(g, __ldg(wd + l + 32 * k), s);
        }
        #pragma unroll
        for (int off = 16; off >= 1; off >>= 1) s += __shfl_xor_sync(0xffffffffu, s, off);
        if (l == 0) out[eg] = sigf(s + __ldg(bd));
    }
}

// ---------------------------------------------------------------------------
extern "C" void kernel_launch(void* const* d_in, const int* in_sizes, int n_in,
                              void* d_out, int out_size) {
    const int*   tokens = (const int*)d_in[0];
    const float* emb = (const float*)d_in[1];
    const float* kx1 = (const float*)d_in[2];
    const float* kh1 = (const float*)d_in[3];
    const float* b1  = (const float*)d_in[4];
    const float* kx2 = (const float*)d_in[5];
    const float* kh2 = (const float*)d_in[6];
    const float* b2  = (const float*)d_in[7];
    const float* wg  = (const float*)d_in[8];
    const float* bg  = (const float*)d_in[9];
    const float* wd  = (const float*)d_in[10];
    const float* bd  = (const float*)d_in[11];
    float* out = (float*)d_out;

    const size_t smem_bytes = SMEM_FLOATS * sizeof(float);
    cudaFuncSetAttribute(rnn_kernel, cudaFuncAttributeMaxDynamicSharedMemorySize, (int)smem_bytes);

    embproj_kernel<<<(VOCAB + 15) / 16, 96>>>(emb, kx1, b1);
    rnn_kernel<<<296, 128, smem_bytes>>>(tokens, kh1, b1, kx2, kh2, b2, wg, bg, wd, bd, out);
}